// round 8
// baseline (speedup 1.0000x reference)
#include <cuda_runtime.h>

#define SS   384
#define SS1  385
#define NH   8
#define NB   32
#define NBH  256          // NB*NH
#define KD   16
#define EPSF 1e-8f
#define GWEPS 0.05f

// ---------------- scratch (static device globals; no allocations) ----------
__device__ float        g_symP[NBH * SS * SS];       // 151 MB
__device__ float        g_deg [NBH * SS];
__device__ unsigned int g_mx  [NBH];
__device__ float        g_a   [NBH * SS];
__device__ float        g_cC1 [NBH * SS];
__device__ float        g_cC2 [NBH * KD];
__device__ float        g_csW [NBH * KD];
__device__ float        g_W   [NBH * SS * KD];
__device__ float        g_tens[NBH * SS * KD];
__device__ float        g_Km  [NBH * SS * KD];
__device__ float        g_alpha[NBH];
__device__ float        g_vh  [NBH * SS1 * 32];

// ---------------------------------------------------------------------------
__global__ void k_zero() {
    int t = blockIdx.x * blockDim.x + threadIdx.x;
    if (t < NBH * SS) g_deg[t] = 0.f;
    if (t < NBH)      g_mx[t]  = 0u;
}

// symmetrize P[1:,1:] -> symP, accumulate rowsums (deg) and global max
// grid: (78 tile-pairs, NBH), block: (32,32)
__global__ void k_sym(const float* __restrict__ P) {
    __shared__ float sA[32][33];
    __shared__ float sB[32][33];
    __shared__ float wm[32];

    int bh = blockIdx.y;
    int p  = blockIdx.x;
    int ti = 0;
    while (p >= 12 - ti) { p -= 12 - ti; ti++; }
    int tj = ti + p;

    int x = threadIdx.x, y = threadIdx.y;
    const float* Pb = P + bh * SS1 * SS1;
    int r0 = ti * 32, c0 = tj * 32;

    sA[y][x] = Pb[(1 + r0 + y) * SS1 + 1 + c0 + x];
    sB[y][x] = Pb[(1 + c0 + y) * SS1 + 1 + r0 + x];
    __syncthreads();

    float* SPb = g_symP + bh * SS * SS;
    float symA = 0.5f * (sA[y][x] + sB[x][y]);
    float symB = 0.5f * (sB[y][x] + sA[x][y]);
    SPb[(r0 + y) * SS + c0 + x] = symA;
    SPb[(c0 + y) * SS + r0 + x] = symB;

    // row sums (deg): A-tile rows always, B-tile rows only if off-diagonal
    float rs = symA;
    #pragma unroll
    for (int off = 16; off; off >>= 1) rs += __shfl_down_sync(0xffffffffu, rs, off);
    if (x == 0) atomicAdd(&g_deg[bh * SS + r0 + y], rs);
    if (ti != tj) {
        float rs2 = symB;
        #pragma unroll
        for (int off = 16; off; off >>= 1) rs2 += __shfl_down_sync(0xffffffffu, rs2, off);
        if (x == 0) atomicAdd(&g_deg[bh * SS + c0 + y], rs2);
    }

    // block max of symA (B-tile values are the same set transposed)
    float m = symA;
    #pragma unroll
    for (int off = 16; off; off >>= 1) m = fmaxf(m, __shfl_down_sync(0xffffffffu, m, off));
    if (x == 0) wm[y] = m;
    __syncthreads();
    if (y == 0) {
        float mm = wm[x];
        #pragma unroll
        for (int off = 16; off; off >>= 1) mm = fmaxf(mm, __shfl_down_sync(0xffffffffu, mm, off));
        if (x == 0) atomicMax(&g_mx[bh], __float_as_uint(mm));
    }
}

// per-bh: a = deg/sum(deg); cC2[l]=sum_k b_k C2[k,l]^2; w0[l]=sum_k b_k C2[l,k];
// W0 = a (x) w0 ; csW0 = w0 * sum(a).   grid: NBH, block: 256
__global__ void k_scalars(const float* __restrict__ DG, const float* __restrict__ bb) {
    __shared__ float red[256];
    __shared__ float sw0[KD];
    int bh = blockIdx.x, t = threadIdx.x;

    float s = 0.f;
    for (int i = t; i < SS; i += 256) s += g_deg[bh * SS + i];
    red[t] = s; __syncthreads();
    for (int off = 128; off; off >>= 1) { if (t < off) red[t] += red[t + off]; __syncthreads(); }
    float sumdeg = red[0];
    float inv = 1.f / fmaxf(sumdeg, EPSF);
    float sa  = sumdeg * inv;          // == 1 unless degenerate

    for (int i = t; i < SS; i += 256) g_a[bh * SS + i] = g_deg[bh * SS + i] * inv;

    if (t < KD) {
        int l = t;
        float c2 = 0.f, w0 = 0.f;
        for (int k = 0; k < KD; k++) {
            float bk  = bb[bh * KD + k];
            float ckl = DG[bh * KD * KD + k * KD + l];
            float clk = DG[bh * KD * KD + l * KD + k];
            c2 += bk * ckl * ckl;
            w0 += bk * clk;
        }
        g_cC2[bh * KD + l] = c2;
        g_csW[bh * KD + l] = w0 * sa;
        sw0[l] = w0;
    }
    __syncthreads();
    for (int idx = t; idx < SS * KD; idx += 256) {
        int i = idx / KD, l = idx % KD;
        g_W[bh * SS * KD + idx] = g_a[bh * SS + i] * sw0[l];
    }
}

// cC1[i] = 1 - 2*r1/mx + r2/mx^2,  r1=sum symP*a, r2=sum symP^2*a
// grid: (6, NBH), block: 256 (8 warps x 8 rows)
__global__ void k_cc1() {
    __shared__ float sa[SS];
    int bh = blockIdx.y, tile = blockIdx.x, t = threadIdx.x;
    for (int i = t; i < SS; i += 256) sa[i] = g_a[bh * SS + i];
    __syncthreads();
    float invm = 1.f / fmaxf(__uint_as_float(g_mx[bh]), EPSF);
    int w = t / 32, lane = t % 32;
    const float* SPb = g_symP + bh * SS * SS;
    for (int rr = 0; rr < 8; rr++) {
        int row = tile * 64 + w * 8 + rr;
        const float* Pr = SPb + row * SS;
        float r1 = 0.f, r2 = 0.f;
        for (int s = lane; s < SS; s += 32) {
            float p = Pr[s], av = sa[s];
            r1 += p * av;
            r2 += p * p * av;
        }
        #pragma unroll
        for (int off = 16; off; off >>= 1) {
            r1 += __shfl_down_sync(0xffffffffu, r1, off);
            r2 += __shfl_down_sync(0xffffffffu, r2, off);
        }
        if (lane == 0)
            g_cC1[bh * SS + row] = 1.f - 2.f * r1 * invm + r2 * invm * invm;
    }
}

// tens = cC1[i] + cC2[l] - 2*(csW[l] - (symP@W)[i,l]/mx); Km = exp(-tens/eps)
// grid: (6, NBH), block: (16,16)
__global__ void k_tens() {
    __shared__ float sW[SS * KD];     // 24 KB
    __shared__ float sP[64 * 65];     // 16.6 KB
    int bh = blockIdx.y, tile = blockIdx.x;
    int l = threadIdx.x, iy = threadIdx.y;
    int t = iy * 16 + l;

    for (int idx = t; idx < SS * KD; idx += 256) sW[idx] = g_W[bh * SS * KD + idx];

    float acc0 = 0.f, acc1 = 0.f, acc2 = 0.f, acc3 = 0.f;
    int i0 = tile * 64;
    const float* SPb = g_symP + bh * SS * SS;

    for (int s0 = 0; s0 < SS; s0 += 64) {
        __syncthreads();
        for (int idx = t; idx < 64 * 64; idx += 256) {
            int r = idx >> 6, ss = idx & 63;
            sP[r * 65 + ss] = SPb[(i0 + r) * SS + s0 + ss];
        }
        __syncthreads();
        #pragma unroll 4
        for (int ss = 0; ss < 64; ss++) {
            float wv = sW[(s0 + ss) * KD + l];
            acc0 += sP[(iy     ) * 65 + ss] * wv;
            acc1 += sP[(iy + 16) * 65 + ss] * wv;
            acc2 += sP[(iy + 32) * 65 + ss] * wv;
            acc3 += sP[(iy + 48) * 65 + ss] * wv;
        }
    }
    float invm = 1.f / fmaxf(__uint_as_float(g_mx[bh]), EPSF);
    float cc2  = g_cC2[bh * KD + l];
    float cs   = g_csW[bh * KD + l];
    const float inve = 1.f / GWEPS;
    float accs[4] = {acc0, acc1, acc2, acc3};
    #pragma unroll
    for (int r4 = 0; r4 < 4; r4++) {
        int i = i0 + iy + 16 * r4;
        float tens = g_cC1[bh * SS + i] + cc2 - 2.f * (cs - accs[r4] * invm);
        int oi = (bh * SS + i) * KD + l;
        g_tens[oi] = tens;
        g_Km[oi]   = __expf(-tens * inve);
    }
}

// sinkhorn (20 iters) entirely in smem; emits W=T*C2^T (+colsum) or alpha on last
// grid: NBH, block: 384
__global__ void k_sink(const float* __restrict__ DG, const float* __restrict__ bglob, int last) {
    __shared__ float sK[SS * 17];     // 26.1 KB, stride-17 pad
    __shared__ float sv[KD];
    __shared__ float sb[KD];
    __shared__ float sC2[KD * KD];
    __shared__ float wpart[12 * KD];
    __shared__ float wsum[12];

    int bh = blockIdx.x, i = threadIdx.x;
    int w = i / 32, lane = i % 32;

    const float4* Kb = reinterpret_cast<const float4*>(g_Km + bh * SS * KD);
    #pragma unroll
    for (int q = 0; q < 4; q++) {
        float4 v4 = Kb[i * 4 + q];
        sK[i * 17 + 4 * q + 0] = v4.x;
        sK[i * 17 + 4 * q + 1] = v4.y;
        sK[i * 17 + 4 * q + 2] = v4.z;
        sK[i * 17 + 4 * q + 3] = v4.w;
    }
    if (i < KD)       { sv[i] = 1.f; sb[i] = bglob[bh * KD + i]; }
    if (i < KD * KD)  sC2[i] = DG[bh * KD * KD + i];
    float a_i = g_a[bh * SS + i];
    __syncthreads();

    float u = 1.f;
    for (int it = 0; it < 20; it++) {
        float s = 0.f;
        #pragma unroll
        for (int k = 0; k < KD; k++) s += sK[i * 17 + k] * sv[k];
        u = a_i / fmaxf(s, 1e-30f);

        float p[KD];
        #pragma unroll
        for (int k = 0; k < KD; k++) p[k] = sK[i * 17 + k] * u;
        #pragma unroll
        for (int k = 0; k < KD; k++)
            #pragma unroll
            for (int off = 16; off; off >>= 1)
                p[k] += __shfl_down_sync(0xffffffffu, p[k], off);
        if (lane == 0) {
            #pragma unroll
            for (int k = 0; k < KD; k++) wpart[w * KD + k] = p[k];
        }
        __syncthreads();
        if (i < KD) {
            float sm = 0.f;
            #pragma unroll
            for (int ww = 0; ww < 12; ww++) sm += wpart[ww * KD + i];
            sv[i] = sb[i] / fmaxf(sm, 1e-30f);
        }
        __syncthreads();
    }

    float Trow[KD];
    #pragma unroll
    for (int k = 0; k < KD; k++) Trow[k] = u * sK[i * 17 + k] * sv[k];

    if (!last) {
        float Wr[KD];
        #pragma unroll
        for (int l = 0; l < KD; l++) {
            float s = 0.f;
            #pragma unroll
            for (int k = 0; k < KD; k++) s += Trow[k] * sC2[l * KD + k];
            Wr[l] = s;
        }
        float4* Wo = reinterpret_cast<float4*>(g_W + (bh * SS + i) * KD);
        Wo[0] = make_float4(Wr[0],  Wr[1],  Wr[2],  Wr[3]);
        Wo[1] = make_float4(Wr[4],  Wr[5],  Wr[6],  Wr[7]);
        Wo[2] = make_float4(Wr[8],  Wr[9],  Wr[10], Wr[11]);
        Wo[3] = make_float4(Wr[12], Wr[13], Wr[14], Wr[15]);
        // column sums of W -> g_csW
        #pragma unroll
        for (int k = 0; k < KD; k++)
            #pragma unroll
            for (int off = 16; off; off >>= 1)
                Wr[k] += __shfl_down_sync(0xffffffffu, Wr[k], off);
        if (lane == 0) {
            #pragma unroll
            for (int k = 0; k < KD; k++) wpart[w * KD + k] = Wr[k];
        }
        __syncthreads();
        if (i < KD) {
            float sm = 0.f;
            #pragma unroll
            for (int ww = 0; ww < 12; ww++) sm += wpart[ww * KD + i];
            g_csW[bh * KD + i] = sm;
        }
    } else {
        const float* tb = g_tens + (bh * SS + i) * KD;
        float g = 0.f;
        #pragma unroll
        for (int k = 0; k < KD; k++) g += tb[k] * Trow[k];
        #pragma unroll
        for (int off = 16; off; off >>= 1) g += __shfl_down_sync(0xffffffffu, g, off);
        if (lane == 0) wsum[w] = g;
        __syncthreads();
        if (i == 0) {
            float tot = 0.f;
            #pragma unroll
            for (int ww = 0; ww < 12; ww++) tot += wsum[ww];
            g_alpha[bh] = expf(-tot);      // sigma = 1
        }
    }
}

// v projection: vh[b,h,s,d] = sum_k nv[b,s,k]*vw[h*32+d,k] + vb
// grid: (193, 4), block: 256
__global__ void k_vproj(const float* __restrict__ nv, const float* __restrict__ vw,
                        const float* __restrict__ vb) {
    __shared__ float sA [64 * 33];
    __shared__ float sWt[64 * 33];
    int m0 = blockIdx.x * 64, n0 = blockIdx.y * 64;
    int t = threadIdx.x, tx = t % 16, ty = t / 16;
    float acc[4][4] = {};

    for (int k0 = 0; k0 < 256; k0 += 32) {
        __syncthreads();
        for (int idx = t; idx < 64 * 32; idx += 256) {
            int r = idx >> 5, kk = idx & 31;
            int m = m0 + r;
            sA [r * 33 + kk] = (m < NB * SS1) ? nv[m * 256 + k0 + kk] : 0.f;
            sWt[r * 33 + kk] = vw[(n0 + r) * 256 + k0 + kk];
        }
        __syncthreads();
        for (int kk = 0; kk < 32; kk++) {
            float ar[4], bc[4];
            #pragma unroll
            for (int r = 0; r < 4; r++) ar[r] = sA [(ty + 16 * r) * 33 + kk];
            #pragma unroll
            for (int c = 0; c < 4; c++) bc[c] = sWt[(tx + 16 * c) * 33 + kk];
            #pragma unroll
            for (int r = 0; r < 4; r++)
                #pragma unroll
                for (int c = 0; c < 4; c++) acc[r][c] += ar[r] * bc[c];
        }
    }
    #pragma unroll
    for (int r = 0; r < 4; r++) {
        int m = m0 + ty + 16 * r;
        if (m >= NB * SS1) continue;
        int b = m / SS1, s = m % SS1;
        #pragma unroll
        for (int c = 0; c < 4; c++) {
            int n = n0 + tx + 16 * c;
            int h = n >> 5, d = n & 31;
            g_vh[((b * NH + h) * SS1 + s) * 32 + d] = acc[r][c] + vb[n];
        }
    }
}

// attn row 0: [0]=0, [1..384]=1/384
__global__ void k_row0(float* __restrict__ attnOut) {
    int bh = blockIdx.x, t = threadIdx.x;
    float* row = attnOut + bh * SS1 * SS1;
    if (t == 0) row[0] = 0.f;
    float v = 1.f / 384.f;
    for (int j = t; j < SS; j += blockDim.x) row[1 + j] = v;
}

// rows 1..384: Q_hat = max(Q,eps)^(1+alpha), diag zeroed, row-normalized
// grid: (6, NBH), block: 256 (8 warps x 8 rows)
__global__ void k_attn(const float* __restrict__ priorQ, float* __restrict__ attnOut) {
    int bh = blockIdx.y, tile = blockIdx.x, t = threadIdx.x;
    int w = t / 32, lane = t % 32;
    float e = 1.f + g_alpha[bh];
    const float* Qb = priorQ + bh * SS * SS;
    float* Ab = attnOut + bh * SS1 * SS1;

    for (int rr = 0; rr < 8; rr++) {
        int r = tile * 64 + w * 8 + rr;
        const float* qrow = Qb + r * SS;
        float tv[12];
        float sum = 0.f;
        #pragma unroll
        for (int c = 0; c < 12; c++) {
            int m = lane + 32 * c;
            float q = fmaxf(qrow[m], EPSF);
            float x = __powf(q, e);
            if (m == r) x = 0.f;
            tv[c] = x;
            sum += x;
        }
        #pragma unroll
        for (int off = 16; off; off >>= 1) sum += __shfl_xor_sync(0xffffffffu, sum, off);
        float inv = 1.f / fmaxf(sum, EPSF);
        float* arow = Ab + (r + 1) * SS1;
        if (lane == 0) arow[0] = 0.f;
        #pragma unroll
        for (int c = 0; c < 12; c++) arow[1 + lane + 32 * c] = tv[c] * inv;
    }
}

// context: basis[b,i,h,d] = sum_j attn[bh,i,j] * vh[bh,j,d]
// grid: (7, NBH), block: 256 (tx=d 0..31, ty row group)
__global__ void k_ctx(const float* __restrict__ attnOut, float* __restrict__ outBasis) {
    __shared__ float sA[64 * 33];
    __shared__ float sV[32 * 33];
    int bh = blockIdx.y, tile = blockIdx.x, t = threadIdx.x;
    int tx = t % 32, ty = t / 32;
    float acc[8] = {};
    const float* Ab = attnOut + bh * SS1 * SS1;
    const float* Vb = g_vh + bh * SS1 * 32;
    int i0 = tile * 64;

    for (int j0 = 0; j0 < SS1; j0 += 32) {
        __syncthreads();
        for (int idx = t; idx < 64 * 32; idx += 256) {
            int r = idx >> 5, jj = idx & 31;
            int i = i0 + r, j = j0 + jj;
            sA[r * 33 + jj] = (i < SS1 && j < SS1) ? Ab[i * SS1 + j] : 0.f;
        }
        for (int idx = t; idx < 32 * 32; idx += 256) {
            int jj = idx >> 5, d = idx & 31;
            int j = j0 + jj;
            sV[jj * 33 + d] = (j < SS1) ? Vb[j * 32 + d] : 0.f;
        }
        __syncthreads();
        #pragma unroll 4
        for (int jj = 0; jj < 32; jj++) {
            float v = sV[jj * 33 + tx];
            #pragma unroll
            for (int r8 = 0; r8 < 8; r8++) acc[r8] += sA[(ty + 8 * r8) * 33 + jj] * v;
        }
    }
    int b = bh >> 3, h = bh & 7;
    #pragma unroll
    for (int r8 = 0; r8 < 8; r8++) {
        int i = i0 + ty + 8 * r8;
        if (i < SS1)
            outBasis[(b * SS1 + i) * 256 + h * 32 + tx] = acc[r8];
    }
}

// ---------------------------------------------------------------------------
extern "C" void kernel_launch(void* const* d_in, const int* in_sizes, int n_in,
                              void* d_out, int out_size) {
    const float* nv = (const float*)d_in[1];   // name_value_embeddings [32,385,256]
    const float* P  = (const float*)d_in[2];   // shared_attn [32,8,385,385]
    const float* Q  = (const float*)d_in[3];   // prior_Q [32,8,384,384]
    const float* DG = (const float*)d_in[4];   // [32,8,16,16]
    const float* bb = (const float*)d_in[5];   // [32,8,16]
    const float* vw = (const float*)d_in[6];   // [256,256]
    const float* vb = (const float*)d_in[7];   // [256]

    float* outB = (float*)d_out;                                   // basis [32,385,8,32]
    float* outA = (float*)d_out + (out_size - NBH * SS1 * SS1);    // attn  [32,8,385,385]

    k_zero   <<<(NBH * SS + 255) / 256, 256>>>();
    k_sym    <<<dim3(78, NBH), dim3(32, 32)>>>(P);
    k_scalars<<<NBH, 256>>>(DG, bb);
    k_cc1    <<<dim3(6, NBH), 256>>>();
    k_vproj  <<<dim3(193, 4), 256>>>(nv, vw, vb);

    for (int it = 0; it < 5; it++) {
        k_tens<<<dim3(6, NBH), dim3(16, 16)>>>();
        k_sink<<<NBH, 384>>>(DG, bb, it == 4 ? 1 : 0);
    }

    k_row0<<<NBH, 128>>>(outA);
    k_attn<<<dim3(6, NBH), 256>>>(Q, outA);
    k_ctx <<<dim3(7, NBH), 256>>>(outA, outB);
}

// round 9
// speedup vs baseline: 1.0006x; 1.0006x over previous
#include <cuda_runtime.h>

#define SS   384
#define SS1  385
#define NH   8
#define NB   32
#define NBH  256          // NB*NH
#define KD   16
#define EPSF 1e-8f
#define GWEPS 0.05f

// ---------------- scratch (static device globals; no allocations) ----------
__device__ float        g_symP[NBH * SS * SS];       // 151 MB
__device__ float        g_deg [NBH * SS];
__device__ unsigned int g_mx  [NBH];
__device__ float        g_a   [NBH * SS];
__device__ float        g_cC1 [NBH * SS];
__device__ float        g_cC2 [NBH * KD];
__device__ float        g_csW [NBH * KD];
__device__ float        g_W   [NBH * SS * KD];
__device__ float        g_tens[NBH * SS * KD];
__device__ float        g_Km  [NBH * SS * KD];
__device__ float        g_alpha[NBH];
__device__ float        g_vh  [NBH * SS1 * 32];

// ---------------------------------------------------------------------------
__global__ void k_zero() {
    int t = blockIdx.x * blockDim.x + threadIdx.x;
    if (t < NBH * SS) g_deg[t] = 0.f;
    if (t < NBH)      g_mx[t]  = 0u;
}

// symmetrize P[1:,1:] -> symP, accumulate rowsums (deg) and global max
// grid: (78 tile-pairs, NBH), block: (32,32)
__global__ void k_sym(const float* __restrict__ P) {
    __shared__ float sA[32][33];
    __shared__ float sB[32][33];
    __shared__ float wm[32];

    int bh = blockIdx.y;
    int p  = blockIdx.x;
    int ti = 0;
    while (p >= 12 - ti) { p -= 12 - ti; ti++; }
    int tj = ti + p;

    int x = threadIdx.x, y = threadIdx.y;
    const float* Pb = P + bh * SS1 * SS1;
    int r0 = ti * 32, c0 = tj * 32;

    sA[y][x] = Pb[(1 + r0 + y) * SS1 + 1 + c0 + x];
    sB[y][x] = Pb[(1 + c0 + y) * SS1 + 1 + r0 + x];
    __syncthreads();

    float* SPb = g_symP + bh * SS * SS;
    float symA = 0.5f * (sA[y][x] + sB[x][y]);
    float symB = 0.5f * (sB[y][x] + sA[x][y]);
    SPb[(r0 + y) * SS + c0 + x] = symA;
    SPb[(c0 + y) * SS + r0 + x] = symB;

    // row sums (deg): A-tile rows always, B-tile rows only if off-diagonal
    float rs = symA;
    #pragma unroll
    for (int off = 16; off; off >>= 1) rs += __shfl_down_sync(0xffffffffu, rs, off);
    if (x == 0) atomicAdd(&g_deg[bh * SS + r0 + y], rs);
    if (ti != tj) {
        float rs2 = symB;
        #pragma unroll
        for (int off = 16; off; off >>= 1) rs2 += __shfl_down_sync(0xffffffffu, rs2, off);
        if (x == 0) atomicAdd(&g_deg[bh * SS + c0 + y], rs2);
    }

    // block max of symA (B-tile values are the same set transposed)
    float m = symA;
    #pragma unroll
    for (int off = 16; off; off >>= 1) m = fmaxf(m, __shfl_down_sync(0xffffffffu, m, off));
    if (x == 0) wm[y] = m;
    __syncthreads();
    if (y == 0) {
        float mm = wm[x];
        #pragma unroll
        for (int off = 16; off; off >>= 1) mm = fmaxf(mm, __shfl_down_sync(0xffffffffu, mm, off));
        if (x == 0) atomicMax(&g_mx[bh], __float_as_uint(mm));
    }
}

// per-bh: a = deg/sum(deg); cC2[l]=sum_k b_k C2[k,l]^2; w0[l]=sum_k b_k C2[l,k];
// W0 = a (x) w0 ; csW0 = w0 * sum(a).   grid: NBH, block: 256
__global__ void k_scalars(const float* __restrict__ DG, const float* __restrict__ bb) {
    __shared__ float red[256];
    __shared__ float sw0[KD];
    int bh = blockIdx.x, t = threadIdx.x;

    float s = 0.f;
    for (int i = t; i < SS; i += 256) s += g_deg[bh * SS + i];
    red[t] = s; __syncthreads();
    for (int off = 128; off; off >>= 1) { if (t < off) red[t] += red[t + off]; __syncthreads(); }
    float sumdeg = red[0];
    float inv = 1.f / fmaxf(sumdeg, EPSF);
    float sa  = sumdeg * inv;          // == 1 unless degenerate

    for (int i = t; i < SS; i += 256) g_a[bh * SS + i] = g_deg[bh * SS + i] * inv;

    if (t < KD) {
        int l = t;
        float c2 = 0.f, w0 = 0.f;
        for (int k = 0; k < KD; k++) {
            float bk  = bb[bh * KD + k];
            float ckl = DG[bh * KD * KD + k * KD + l];
            float clk = DG[bh * KD * KD + l * KD + k];
            c2 += bk * ckl * ckl;
            w0 += bk * clk;
        }
        g_cC2[bh * KD + l] = c2;
        g_csW[bh * KD + l] = w0 * sa;
        sw0[l] = w0;
    }
    __syncthreads();
    for (int idx = t; idx < SS * KD; idx += 256) {
        int i = idx / KD, l = idx % KD;
        g_W[bh * SS * KD + idx] = g_a[bh * SS + i] * sw0[l];
    }
}

// cC1[i] = 1 - 2*r1/mx + r2/mx^2,  r1=sum symP*a, r2=sum symP^2*a
// grid: (6, NBH), block: 256 (8 warps x 8 rows)
__global__ void k_cc1() {
    __shared__ float sa[SS];
    int bh = blockIdx.y, tile = blockIdx.x, t = threadIdx.x;
    for (int i = t; i < SS; i += 256) sa[i] = g_a[bh * SS + i];
    __syncthreads();
    float invm = 1.f / fmaxf(__uint_as_float(g_mx[bh]), EPSF);
    int w = t / 32, lane = t % 32;
    const float* SPb = g_symP + bh * SS * SS;
    for (int rr = 0; rr < 8; rr++) {
        int row = tile * 64 + w * 8 + rr;
        const float* Pr = SPb + row * SS;
        float r1 = 0.f, r2 = 0.f;
        for (int s = lane; s < SS; s += 32) {
            float p = Pr[s], av = sa[s];
            r1 += p * av;
            r2 += p * p * av;
        }
        #pragma unroll
        for (int off = 16; off; off >>= 1) {
            r1 += __shfl_down_sync(0xffffffffu, r1, off);
            r2 += __shfl_down_sync(0xffffffffu, r2, off);
        }
        if (lane == 0)
            g_cC1[bh * SS + row] = 1.f - 2.f * r1 * invm + r2 * invm * invm;
    }
}

// tens = cC1[i] + cC2[l] - 2*(csW[l] - (symP@W)[i,l]/mx); Km = exp(-tens/eps)
// grid: (6, NBH), block: (16,16)
__global__ void k_tens() {
    __shared__ float sW[SS * KD];     // 24 KB
    __shared__ float sP[64 * 65];     // 16.6 KB
    int bh = blockIdx.y, tile = blockIdx.x;
    int l = threadIdx.x, iy = threadIdx.y;
    int t = iy * 16 + l;

    for (int idx = t; idx < SS * KD; idx += 256) sW[idx] = g_W[bh * SS * KD + idx];

    float acc0 = 0.f, acc1 = 0.f, acc2 = 0.f, acc3 = 0.f;
    int i0 = tile * 64;
    const float* SPb = g_symP + bh * SS * SS;

    for (int s0 = 0; s0 < SS; s0 += 64) {
        __syncthreads();
        for (int idx = t; idx < 64 * 64; idx += 256) {
            int r = idx >> 6, ss = idx & 63;
            sP[r * 65 + ss] = SPb[(i0 + r) * SS + s0 + ss];
        }
        __syncthreads();
        #pragma unroll 4
        for (int ss = 0; ss < 64; ss++) {
            float wv = sW[(s0 + ss) * KD + l];
            acc0 += sP[(iy     ) * 65 + ss] * wv;
            acc1 += sP[(iy + 16) * 65 + ss] * wv;
            acc2 += sP[(iy + 32) * 65 + ss] * wv;
            acc3 += sP[(iy + 48) * 65 + ss] * wv;
        }
    }
    float invm = 1.f / fmaxf(__uint_as_float(g_mx[bh]), EPSF);
    float cc2  = g_cC2[bh * KD + l];
    float cs   = g_csW[bh * KD + l];
    const float inve = 1.f / GWEPS;
    float accs[4] = {acc0, acc1, acc2, acc3};
    #pragma unroll
    for (int r4 = 0; r4 < 4; r4++) {
        int i = i0 + iy + 16 * r4;
        float tens = g_cC1[bh * SS + i] + cc2 - 2.f * (cs - accs[r4] * invm);
        int oi = (bh * SS + i) * KD + l;
        g_tens[oi] = tens;
        g_Km[oi]   = __expf(-tens * inve);
    }
}

// sinkhorn (20 iters) entirely in smem; emits W=T*C2^T (+colsum) or alpha on last
// grid: NBH, block: 384
__global__ void k_sink(const float* __restrict__ DG, const float* __restrict__ bglob, int last) {
    __shared__ float sK[SS * 17];     // 26.1 KB, stride-17 pad
    __shared__ float sv[KD];
    __shared__ float sb[KD];
    __shared__ float sC2[KD * KD];
    __shared__ float wpart[12 * KD];
    __shared__ float wsum[12];

    int bh = blockIdx.x, i = threadIdx.x;
    int w = i / 32, lane = i % 32;

    const float4* Kb = reinterpret_cast<const float4*>(g_Km + bh * SS * KD);
    #pragma unroll
    for (int q = 0; q < 4; q++) {
        float4 v4 = Kb[i * 4 + q];
        sK[i * 17 + 4 * q + 0] = v4.x;
        sK[i * 17 + 4 * q + 1] = v4.y;
        sK[i * 17 + 4 * q + 2] = v4.z;
        sK[i * 17 + 4 * q + 3] = v4.w;
    }
    if (i < KD)       { sv[i] = 1.f; sb[i] = bglob[bh * KD + i]; }
    if (i < KD * KD)  sC2[i] = DG[bh * KD * KD + i];
    float a_i = g_a[bh * SS + i];
    __syncthreads();

    float u = 1.f;
    for (int it = 0; it < 20; it++) {
        float s = 0.f;
        #pragma unroll
        for (int k = 0; k < KD; k++) s += sK[i * 17 + k] * sv[k];
        u = a_i / fmaxf(s, 1e-30f);

        float p[KD];
        #pragma unroll
        for (int k = 0; k < KD; k++) p[k] = sK[i * 17 + k] * u;
        #pragma unroll
        for (int k = 0; k < KD; k++)
            #pragma unroll
            for (int off = 16; off; off >>= 1)
                p[k] += __shfl_down_sync(0xffffffffu, p[k], off);
        if (lane == 0) {
            #pragma unroll
            for (int k = 0; k < KD; k++) wpart[w * KD + k] = p[k];
        }
        __syncthreads();
        if (i < KD) {
            float sm = 0.f;
            #pragma unroll
            for (int ww = 0; ww < 12; ww++) sm += wpart[ww * KD + i];
            sv[i] = sb[i] / fmaxf(sm, 1e-30f);
        }
        __syncthreads();
    }

    float Trow[KD];
    #pragma unroll
    for (int k = 0; k < KD; k++) Trow[k] = u * sK[i * 17 + k] * sv[k];

    if (!last) {
        float Wr[KD];
        #pragma unroll
        for (int l = 0; l < KD; l++) {
            float s = 0.f;
            #pragma unroll
            for (int k = 0; k < KD; k++) s += Trow[k] * sC2[l * KD + k];
            Wr[l] = s;
        }
        float4* Wo = reinterpret_cast<float4*>(g_W + (bh * SS + i) * KD);
        Wo[0] = make_float4(Wr[0],  Wr[1],  Wr[2],  Wr[3]);
        Wo[1] = make_float4(Wr[4],  Wr[5],  Wr[6],  Wr[7]);
        Wo[2] = make_float4(Wr[8],  Wr[9],  Wr[10], Wr[11]);
        Wo[3] = make_float4(Wr[12], Wr[13], Wr[14], Wr[15]);
        // column sums of W -> g_csW
        #pragma unroll
        for (int k = 0; k < KD; k++)
            #pragma unroll
            for (int off = 16; off; off >>= 1)
                Wr[k] += __shfl_down_sync(0xffffffffu, Wr[k], off);
        if (lane == 0) {
            #pragma unroll
            for (int k = 0; k < KD; k++) wpart[w * KD + k] = Wr[k];
        }
        __syncthreads();
        if (i < KD) {
            float sm = 0.f;
            #pragma unroll
            for (int ww = 0; ww < 12; ww++) sm += wpart[ww * KD + i];
            g_csW[bh * KD + i] = sm;
        }
    } else {
        const float* tb = g_tens + (bh * SS + i) * KD;
        float g = 0.f;
        #pragma unroll
        for (int k = 0; k < KD; k++) g += tb[k] * Trow[k];
        #pragma unroll
        for (int off = 16; off; off >>= 1) g += __shfl_down_sync(0xffffffffu, g, off);
        if (lane == 0) wsum[w] = g;
        __syncthreads();
        if (i == 0) {
            float tot = 0.f;
            #pragma unroll
            for (int ww = 0; ww < 12; ww++) tot += wsum[ww];
            g_alpha[bh] = expf(-tot);      // sigma = 1
        }
    }
}

// v projection: vh[b,h,s,d] = sum_k nv[b,s,k]*vw[h*32+d,k] + vb
// grid: (193, 4), block: 256
__global__ void k_vproj(const float* __restrict__ nv, const float* __restrict__ vw,
                        const float* __restrict__ vb) {
    __shared__ float sA [64 * 33];
    __shared__ float sWt[64 * 33];
    int m0 = blockIdx.x * 64, n0 = blockIdx.y * 64;
    int t = threadIdx.x, tx = t % 16, ty = t / 16;
    float acc[4][4] = {};

    for (int k0 = 0; k0 < 256; k0 += 32) {
        __syncthreads();
        for (int idx = t; idx < 64 * 32; idx += 256) {
            int r = idx >> 5, kk = idx & 31;
            int m = m0 + r;
            sA [r * 33 + kk] = (m < NB * SS1) ? nv[m * 256 + k0 + kk] : 0.f;
            sWt[r * 33 + kk] = vw[(n0 + r) * 256 + k0 + kk];
        }
        __syncthreads();
        for (int kk = 0; kk < 32; kk++) {
            float ar[4], bc[4];
            #pragma unroll
            for (int r = 0; r < 4; r++) ar[r] = sA [(ty + 16 * r) * 33 + kk];
            #pragma unroll
            for (int c = 0; c < 4; c++) bc[c] = sWt[(tx + 16 * c) * 33 + kk];
            #pragma unroll
            for (int r = 0; r < 4; r++)
                #pragma unroll
                for (int c = 0; c < 4; c++) acc[r][c] += ar[r] * bc[c];
        }
    }
    #pragma unroll
    for (int r = 0; r < 4; r++) {
        int m = m0 + ty + 16 * r;
        if (m >= NB * SS1) continue;
        int b = m / SS1, s = m % SS1;
        #pragma unroll
        for (int c = 0; c < 4; c++) {
            int n = n0 + tx + 16 * c;
            int h = n >> 5, d = n & 31;
            g_vh[((b * NH + h) * SS1 + s) * 32 + d] = acc[r][c] + vb[n];
        }
    }
}

// attn row 0: [0]=0, [1..384]=1/384
__global__ void k_row0(float* __restrict__ attnOut) {
    int bh = blockIdx.x, t = threadIdx.x;
    float* row = attnOut + bh * SS1 * SS1;
    if (t == 0) row[0] = 0.f;
    float v = 1.f / 384.f;
    for (int j = t; j < SS; j += blockDim.x) row[1 + j] = v;
}

// rows 1..384: Q_hat = max(Q,eps)^(1+alpha), diag zeroed, row-normalized
// grid: (6, NBH), block: 256 (8 warps x 8 rows)
__global__ void k_attn(const float* __restrict__ priorQ, float* __restrict__ attnOut) {
    int bh = blockIdx.y, tile = blockIdx.x, t = threadIdx.x;
    int w = t / 32, lane = t % 32;
    float e = 1.f + g_alpha[bh];
    const float* Qb = priorQ + bh * SS * SS;
    float* Ab = attnOut + bh * SS1 * SS1;

    for (int rr = 0; rr < 8; rr++) {
        int r = tile * 64 + w * 8 + rr;
        const float* qrow = Qb + r * SS;
        float tv[12];
        float sum = 0.f;
        #pragma unroll
        for (int c = 0; c < 12; c++) {
            int m = lane + 32 * c;
            float q = fmaxf(qrow[m], EPSF);
            float x = __powf(q, e);
            if (m == r) x = 0.f;
            tv[c] = x;
            sum += x;
        }
        #pragma unroll
        for (int off = 16; off; off >>= 1) sum += __shfl_xor_sync(0xffffffffu, sum, off);
        float inv = 1.f / fmaxf(sum, EPSF);
        float* arow = Ab + (r + 1) * SS1;
        if (lane == 0) arow[0] = 0.f;
        #pragma unroll
        for (int c = 0; c < 12; c++) arow[1 + lane + 32 * c] = tv[c] * inv;
    }
}

// context: basis[b,i,h,d] = sum_j attn[bh,i,j] * vh[bh,j,d]
// grid: (7, NBH), block: 256 (tx=d 0..31, ty row group)
__global__ void k_ctx(const float* __restrict__ attnOut, float* __restrict__ outBasis) {
    __shared__ float sA[64 * 33];
    __shared__ float sV[32 * 33];
    int bh = blockIdx.y, tile = blockIdx.x, t = threadIdx.x;
    int tx = t % 32, ty = t / 32;
    float acc[8] = {};
    const float* Ab = attnOut + bh * SS1 * SS1;
    const float* Vb = g_vh + bh * SS1 * 32;
    int i0 = tile * 64;

    for (int j0 = 0; j0 < SS1; j0 += 32) {
        __syncthreads();
        for (int idx = t; idx < 64 * 32; idx += 256) {
            int r = idx >> 5, jj = idx & 31;
            int i = i0 + r, j = j0 + jj;
            sA[r * 33 + jj] = (i < SS1 && j < SS1) ? Ab[i * SS1 + j] : 0.f;
        }
        for (int idx = t; idx < 32 * 32; idx += 256) {
            int jj = idx >> 5, d = idx & 31;
            int j = j0 + jj;
            sV[jj * 33 + d] = (j < SS1) ? Vb[j * 32 + d] : 0.f;
        }
        __syncthreads();
        #pragma unroll 4
        for (int jj = 0; jj < 32; jj++) {
            float v = sV[jj * 33 + tx];
            #pragma unroll
            for (int r8 = 0; r8 < 8; r8++) acc[r8] += sA[(ty + 8 * r8) * 33 + jj] * v;
        }
    }
    int b = bh >> 3, h = bh & 7;
    #pragma unroll
    for (int r8 = 0; r8 < 8; r8++) {
        int i = i0 + ty + 8 * r8;
        if (i < SS1)
            outBasis[(b * SS1 + i) * 256 + h * 32 + tx] = acc[r8];
    }
}

// ---------------------------------------------------------------------------
extern "C" void kernel_launch(void* const* d_in, const int* in_sizes, int n_in,
                              void* d_out, int out_size) {
    const float* nv = (const float*)d_in[1];   // name_value_embeddings [32,385,256]
    const float* P  = (const float*)d_in[2];   // shared_attn [32,8,385,385]
    const float* Q  = (const float*)d_in[3];   // prior_Q [32,8,384,384]
    const float* DG = (const float*)d_in[4];   // [32,8,16,16]
    const float* bb = (const float*)d_in[5];   // [32,8,16]
    const float* vw = (const float*)d_in[6];   // [256,256]
    const float* vb = (const float*)d_in[7];   // [256]

    float* outB = (float*)d_out;                                   // basis [32,385,8,32]
    float* outA = (float*)d_out + (out_size - NBH * SS1 * SS1);    // attn  [32,8,385,385]

    k_zero   <<<(NBH * SS + 255) / 256, 256>>>();
    k_sym    <<<dim3(78, NBH), dim3(32, 32)>>>(P);
    k_scalars<<<NBH, 256>>>(DG, bb);
    k_cc1    <<<dim3(6, NBH), 256>>>();
    k_vproj  <<<dim3(193, 4), 256>>>(nv, vw, vb);

    for (int it = 0; it < 5; it++) {
        k_tens<<<dim3(6, NBH), dim3(16, 16)>>>();
        k_sink<<<NBH, 384>>>(DG, bb, it == 4 ? 1 : 0);
    }

    k_row0<<<NBH, 128>>>(outA);
    k_attn<<<dim3(6, NBH), 256>>>(Q, outA);
    k_ctx <<<dim3(7, NBH), 256>>>(outA, outB);
}